// round 1
// baseline (speedup 1.0000x reference)
#include <cuda_runtime.h>

// DPLoss: masked per-row MSE of (pred - log(alignment)), normalized by row
// length, then mean over batch.
//
// Inputs (metadata order):
//   d_in[0] = pred            float32 [B, T]
//   d_in[1] = alignment       float32 [B, T]
//   d_in[2] = token_lengths   int32   [B]
// Output: scalar float32.
//
// HBM-bound: we read only ceil(len/4) float4 vectors per row per tensor
// (~half the raw footprint given uniform lengths), reduce within the CTA,
// and atomically accumulate sum/(len*B) into d_out[0].

__global__ void dploss_zero(float* __restrict__ out) {
    if (threadIdx.x == 0) out[0] = 0.0f;
}

__global__ __launch_bounds__(256) void dploss_kernel(
    const float* __restrict__ pred,
    const float* __restrict__ alignment,
    const int*   __restrict__ lens,
    float* __restrict__ out,
    int T, float inv_B)
{
    const int row = blockIdx.x;
    const int len = lens[row];

    const float4* __restrict__ p4 =
        reinterpret_cast<const float4*>(pred + (size_t)row * T);
    const float4* __restrict__ a4 =
        reinterpret_cast<const float4*>(alignment + (size_t)row * T);

    const int nvec = (len + 3) >> 2;   // float4 vectors to touch in this row

    float acc = 0.0f;

    for (int v = threadIdx.x; v < nvec; v += blockDim.x) {
        const float4 p = p4[v];
        const float4 a = a4[v];
        const int base = v << 2;

        if (base + 4 <= len) {
            // fully valid vector (common case)
            float d0 = p.x - __logf(a.x);
            float d1 = p.y - __logf(a.y);
            float d2 = p.z - __logf(a.z);
            float d3 = p.w - __logf(a.w);
            acc = fmaf(d0, d0, acc);
            acc = fmaf(d1, d1, acc);
            acc = fmaf(d2, d2, acc);
            acc = fmaf(d3, d3, acc);
        } else {
            // tail vector: mask per lane (padded alignment > 0, log is safe,
            // but we must exclude it from the sum)
            if (base + 0 < len) { float d = p.x - __logf(a.x); acc = fmaf(d, d, acc); }
            if (base + 1 < len) { float d = p.y - __logf(a.y); acc = fmaf(d, d, acc); }
            if (base + 2 < len) { float d = p.z - __logf(a.z); acc = fmaf(d, d, acc); }
            if (base + 3 < len) { float d = p.w - __logf(a.w); acc = fmaf(d, d, acc); }
        }
    }

    // ---- block reduction: warp shuffle, then smem across warps ----
    #pragma unroll
    for (int off = 16; off > 0; off >>= 1)
        acc += __shfl_xor_sync(0xFFFFFFFFu, acc, off);

    __shared__ float warp_sums[8];   // 256 threads = 8 warps
    const int wid = threadIdx.x >> 5;
    const int lid = threadIdx.x & 31;
    if (lid == 0) warp_sums[wid] = acc;
    __syncthreads();

    if (wid == 0) {
        float s = (lid < 8) ? warp_sums[lid] : 0.0f;
        #pragma unroll
        for (int off = 4; off > 0; off >>= 1)
            s += __shfl_xor_sync(0xFFFFFFFFu, s, off);
        if (lid == 0) {
            // per_sample_mse / B, accumulated across rows
            atomicAdd(out, s * inv_B / (float)len);
        }
    }
}

extern "C" void kernel_launch(void* const* d_in, const int* in_sizes, int n_in,
                              void* d_out, int out_size)
{
    const float* pred      = (const float*)d_in[0];
    const float* alignment = (const float*)d_in[1];
    const int*   lens      = (const int*)d_in[2];
    float*       out       = (float*)d_out;

    const int B = in_sizes[2];             // token_lengths element count
    const int T = in_sizes[0] / B;         // pred is [B, T]

    dploss_zero<<<1, 32>>>(out);
    dploss_kernel<<<B, 256>>>(pred, alignment, lens, out, T, 1.0f / (float)B);
}